// round 12
// baseline (speedup 1.0000x reference)
#include <cuda_runtime.h>
#include <cuda_fp16.h>
#include <cstdint>

// C = tril( tril(A) @ tril(B) ), N=4096 fp32.
// Single-pass fp16 HMMA GEMM. CTA tile 128x256, warp tile 64x64 (8 warps),
// BK=64, 3-stage cp.async pipeline. Lower-tri tiles only, LPT order,
// zero-fill CTAs fused. No epilogue masking needed: operand tril masks make
// all above-diagonal outputs exactly 0 (unwritten g_Bhi tiles are
// zero-initialized device globals).

#define NN 4096

// ---------------- scratch (device globals; no allocation allowed) ----------
__device__ __half g_Ahi[(size_t)NN * NN];   // [m][k], tril-masked fp16
__device__ __half g_Bhi[(size_t)NN * NN];   // transposed: [n][k], tril-masked

// ---------------- conversion kernels ---------------------------------------
__global__ __launch_bounds__(256) void convA_kernel(const float* __restrict__ A) {
    const int tk = blockIdx.x, ti = blockIdx.y;
    if (tk > ti) return;
    const int tid = threadIdx.x;
    #pragma unroll
    for (int l = 0; l < 8; l++) {
        int idx = tid + (l << 8);          // 0..2047
        int r = idx >> 4;                  // 0..127
        int c = (idx & 15) << 3;           // 0..120
        int gi = ti * 128 + r;
        int gk = tk * 128 + c;
        const float* p = A + ((long)gi << 12) + gk;
        float4 v0 = *(const float4*)p;
        float4 v1 = *(const float4*)(p + 4);
        float f[8] = {v0.x, v0.y, v0.z, v0.w, v1.x, v1.y, v1.z, v1.w};
        __align__(16) __half h[8];
        #pragma unroll
        for (int e = 0; e < 8; e++)
            h[e] = __float2half((gk + e <= gi) ? f[e] : 0.f);
        *(uint4*)(g_Ahi + ((long)gi << 12) + gk) = *(const uint4*)h;
    }
}

__global__ __launch_bounds__(256) void convB_kernel(const float* __restrict__ B) {
    const int bx = blockIdx.x;  // n 64-tile
    const int by = blockIdx.y;  // k 64-tile
    if ((by >> 1) < (bx >> 1)) return;
    __shared__ float sm[64][65];
    const int tid = threadIdx.x;
    #pragma unroll
    for (int p = 0; p < 16; p++) {
        int idx = tid + 256 * p;
        int r = idx >> 6, c = idx & 63;
        sm[r][c] = B[((long)(by * 64 + r) << 12) + bx * 64 + c];
    }
    __syncthreads();
    #pragma unroll
    for (int p = 0; p < 2; p++) {
        int idx = tid + 256 * p;
        int n = idx >> 3;
        int k8 = (idx & 7) << 3;
        int gn = bx * 64 + n;
        __align__(16) __half h[8];
        #pragma unroll
        for (int e = 0; e < 8; e++) {
            int gk = by * 64 + k8 + e;
            float v = sm[k8 + e][n];
            h[e] = __float2half((gk >= gn) ? v : 0.f);
        }
        *(uint4*)(g_Bhi + ((long)gn << 12) + by * 64 + k8) = *(const uint4*)h;
    }
}

// ---------------- HMMA GEMM kernel ------------------------------------------
// CTA tile 128(m) x 256(n), BK=64, 8 warps (2x4), warp tile 64x64.
// Stage: A 128 rows x 144 B, B 256 rows x 144 B (128 data + 16 pad). 3 stages.

#define ROWB 144
#define A_MATB (128 * ROWB)          // 18432
#define B_MATB (256 * ROWB)          // 36864
#define STGB (A_MATB + B_MATB)       // 55296
#define SMEM_TOTAL (3 * STGB)        // 165888
#define NCOMP 272                    // compute CTAs
#define NZERO 240                    // zero-fill CTAs

__device__ __forceinline__ void cp16(uint32_t s, const void* g) {
    asm volatile("cp.async.cg.shared.global [%0], [%1], 16;"
                 :: "r"(s), "l"(__cvta_generic_to_global(g)));
}
#define CP_COMMIT() asm volatile("cp.async.commit_group;" ::: "memory")
#define CP_WAIT1()  asm volatile("cp.async.wait_group 1;" ::: "memory")

#define LDSM4(r0, r1, r2, r3, addr)                                          \
    asm volatile("ldmatrix.sync.aligned.m8n8.x4.shared.b16 {%0,%1,%2,%3}, [%4];" \
                 : "=r"(r0), "=r"(r1), "=r"(r2), "=r"(r3) : "r"(addr))

#define MMA(d, a, b)                                                         \
    asm volatile("mma.sync.aligned.m16n8k16.row.col.f32.f16.f16.f32 "        \
                 "{%0,%1,%2,%3},{%4,%5,%6,%7},{%8,%9},{%0,%1,%2,%3};"        \
                 : "+f"((d)[0]), "+f"((d)[1]), "+f"((d)[2]), "+f"((d)[3])    \
                 : "r"((a)[0]), "r"((a)[1]), "r"((a)[2]), "r"((a)[3]),       \
                   "r"((b)[0]), "r"((b)[1]))

__global__ __launch_bounds__(256, 1)
void trimm_mma_kernel(float* __restrict__ C) {
    extern __shared__ char smem[];
    const uint32_t sb = (uint32_t)__cvta_generic_to_shared(smem);
    const int tid = threadIdx.x;
    const int wid = tid >> 5;
    const int lane = tid & 31;
    const int wm = wid >> 2;     // 0..1  (m 64-half)
    const int wn = wid & 3;      // 0..3  (n 64-quarter)

    // ---- zero-fill CTAs: tiles fully above the diagonal ----
    if (blockIdx.x >= NCOMP) {
        int z = blockIdx.x - NCOMP;
        int bi;
        for (bi = 0; bi < 32; bi++) {
            int c = 15 - (bi >> 1);            // zero tiles in this row
            if (z < c) break;
            z -= c;
        }
        const int bj2 = (bi >> 1) + 1 + z;     // first fully-zero col tile + z
        const float4 zero = make_float4(0.f, 0.f, 0.f, 0.f);
        #pragma unroll
        for (int l = 0; l < 32; l++) {
            int idx = tid + (l << 8);          // 0..8191
            int r = idx >> 6;                  // 0..127
            int v = idx & 63;                  // float4 within 256 cols
            *(float4*)(C + (((long)(bi * 128 + r)) << 12) + bj2 * 256 + v * 4) = zero;
        }
        return;
    }

    // ---- map blockIdx -> (bi, bj2): longest k first (d2 descending) ----
    int t = blockIdx.x, d2;
    for (d2 = 31; d2 > 0; d2--) {
        int c = ((31 - d2) >> 1) + 1;
        if (t < c) break;
        t -= c;
    }
    const int bj2 = t;
    const int bi = d2 + 2 * t;
    const int rowBase = bi << 7;
    const int colBase = bj2 << 8;
    const int T = 2 * (d2 + 1);              // BK=64 k-tiles (>= 2)

    float acc[4][8][4];
    #pragma unroll
    for (int i = 0; i < 4; i++)
        #pragma unroll
        for (int j = 0; j < 8; j++)
            #pragma unroll
            for (int e = 0; e < 4; e++) acc[i][j][e] = 0.f;

    const int arow = lane & 15;
    const int asel = lane >> 4;
    const int brow = (((lane >> 4) & 1) << 3) + (lane & 7);
    const int bsel = (lane >> 3) & 1;

    // stage loader: A 1024 + B 2048 16B chunks = 12 per thread.
    auto load_stage = [&](int slot, int k0) {
        uint32_t sbase = sb + slot * STGB;
        #pragma unroll
        for (int l = 0; l < 4; l++) {          // A: 1024 chunks
            int idx = tid + (l << 8);          // 0..1023
            int rr = idx >> 3;                 // 0..127
            int cv = idx & 7;
            cp16(sbase + rr * ROWB + cv * 16,
                 g_Ahi + (((long)(rowBase + rr)) << 12) + k0 + (cv << 3));
        }
        #pragma unroll
        for (int l = 0; l < 8; l++) {          // B: 2048 chunks
            int idx = tid + (l << 8);          // 0..2047
            int rr = idx >> 3;                 // 0..255
            int cv = idx & 7;
            cp16(sbase + A_MATB + rr * ROWB + cv * 16,
                 g_Bhi + (((long)(colBase + rr)) << 12) + k0 + (cv << 3));
        }
    };

    load_stage(0, colBase);
    CP_COMMIT();
    load_stage(1, colBase + 64);
    CP_COMMIT();

    for (int tt = 0; tt < T; tt++) {
        CP_WAIT1();                           // stage tt resident
        __syncthreads();                      // all warps done with slot (tt+2)%3
        if (tt + 2 < T)
            load_stage((tt + 2) % 3, colBase + ((tt + 2) << 6));
        CP_COMMIT();                          // uniform group count

        const uint32_t sbase = sb + (tt % 3) * STGB;
        const uint32_t aBase = sbase + (wm * 64 + arow) * ROWB + asel * 16;
        const uint32_t bBase = sbase + A_MATB + (wn * 64 + brow) * ROWB + bsel * 16;

        #pragma unroll
        for (int ks = 0; ks < 4; ks++) {      // four k=16 steps in BK=64
            uint32_t ah[4][4];
            #pragma unroll
            for (int i = 0; i < 4; i++) {
                uint32_t ad = aBase + i * (16 * ROWB) + ks * 32;
                LDSM4(ah[i][0], ah[i][1], ah[i][2], ah[i][3], ad);
            }
            #pragma unroll
            for (int p = 0; p < 4; p++) {     // four n16 chunks = n64
                uint32_t b0[2], b1[2];
                {
                    uint32_t r0, r1, r2, r3;
                    LDSM4(r0, r1, r2, r3, bBase + p * (16 * ROWB) + ks * 32);
                    b0[0] = r0; b0[1] = r1;
                    b1[0] = r2; b1[1] = r3;
                }
                #pragma unroll
                for (int i = 0; i < 4; i++) {
                    MMA(acc[i][2 * p], ah[i], b0);
                    MMA(acc[i][2 * p + 1], ah[i], b1);
                }
            }
        }
    }

    // ---- epilogue: plain stores (upper-diag entries are exactly 0) ----
    #pragma unroll
    for (int i = 0; i < 4; i++) {
        #pragma unroll
        for (int j = 0; j < 8; j++) {
            int r0 = rowBase + wm * 64 + i * 16 + (lane >> 2);
            int c0 = colBase + wn * 64 + j * 8 + (lane & 3) * 2;
            *(float2*)(C + ((long)r0 << 12) + c0) =
                make_float2(acc[i][j][0], acc[i][j][1]);
            *(float2*)(C + ((long)(r0 + 8) << 12) + c0) =
                make_float2(acc[i][j][2], acc[i][j][3]);
        }
    }
}

// ---------------- launcher --------------------------------------------------
extern "C" void kernel_launch(void* const* d_in, const int* in_sizes, int n_in,
                              void* d_out, int out_size) {
    const float* A = (const float*)d_in[0];
    const float* B = (const float*)d_in[1];
    float* C = (float*)d_out;

    cudaFuncSetAttribute(trimm_mma_kernel,
                         cudaFuncAttributeMaxDynamicSharedMemorySize, SMEM_TOTAL);

    convA_kernel<<<dim3(32, 32), 256>>>(A);
    convB_kernel<<<dim3(64, 64), 256>>>(B);
    trimm_mma_kernel<<<NCOMP + NZERO, 256, SMEM_TOTAL>>>(C);
}